// round 17
// baseline (speedup 1.0000x reference)
#include <cuda_runtime.h>
#include <cuda_fp16.h>
#include <cstdint>
#include <cstddef>

#define Bsz  64
#define Tlen 4096
#define DIN  64
#define DEMB 24
#define Hdim 128

// Scratch (static device globals — no allocation in kernel_launch)
__device__ __half g_u16[(size_t)Bsz * Tlen * 4 * Hdim];   // 256 MB, layout [row][j*4+gate]
__device__ int    g_done[Bsz];                            // per-batch chunk ticket (zero-init; reset by scan)

__device__ __forceinline__ float tanhfast(float x) {
    float y;
    asm("tanh.approx.f32 %0, %1;" : "=f"(y) : "f"(x));
    return y;
}
__device__ __forceinline__ float fsigmoid(float z) {
    return fmaf(0.5f, tanhfast(0.5f * z), 0.5f);
}
__device__ __forceinline__ __half2 tanh2fast(__half2 x) {
    uint32_t xi = *reinterpret_cast<uint32_t*>(&x);
    uint32_t yi;
    asm("tanh.approx.f16x2 %0, %1;" : "=r"(yi) : "r"(xi));
    return *reinterpret_cast<__half2*>(&yi);
}

// ---------------------------------------------------------------------------
// Fused kernel.
//  blocks [0,64):        scan, one batch each (exclusive SM: 255 regs/thread)
//  blocks [64, 64+8192): producer p = blk-64: batch b = p&63, chunk k = p>>6
//                        (k-major => early timesteps produced first; ticket
//                        chain makes done[b]*32 a prefix-complete row count)
// ---------------------------------------------------------------------------
__global__ void __launch_bounds__(256, 1) fused_kernel(
    const float* __restrict__ x,
    const float* __restrict__ W_emb, const float* __restrict__ b_emb,
    const float* __restrict__ Wf, const float* __restrict__ bf,
    const float* __restrict__ Wi, const float* __restrict__ bi,
    const float* __restrict__ Wc, const float* __restrict__ bc,
    const float* __restrict__ Wo, const float* __restrict__ bo,
    const float* __restrict__ W_out, const float* __restrict__ b_out,
    float* __restrict__ out)
{
    const int tid = threadIdx.x;

    if (blockIdx.x >= 64) {
        // =================== PRODUCER ===================
        const int p  = blockIdx.x - 64;
        const int b  = p & 63;
        const int k  = p >> 6;              // chunk 0..127
        const size_t r0 = (size_t)b * Tlen + (size_t)k * 32;   // first global row

        __shared__ float xs[32][DIN];       // 8 KB
        __shared__ float ws[DIN * DEMB];    // 6 KB
        __shared__ float bs[DEMB];
        __shared__ float es[32][DEMB];      // 3 KB

        {
            const float4* xsrc = reinterpret_cast<const float4*>(x + r0 * DIN);
            float4* xdst = reinterpret_cast<float4*>(&xs[0][0]);
#pragma unroll
            for (int i = 0; i < 2; i++) xdst[tid + 256 * i] = xsrc[tid + 256 * i];
            for (int i = tid; i < DIN * DEMB; i += 256) ws[i] = W_emb[i];
            if (tid < DEMB) bs[tid] = b_emb[tid];
        }
        __syncthreads();

        // e = sigmoid(x @ W_emb + b): thread -> (row = tid>>3, 3 outputs)
        {
            const int r  = tid >> 3;
            const int j0 = (tid & 7) * 3;
            float a0 = bs[j0], a1 = bs[j0 + 1], a2 = bs[j0 + 2];
#pragma unroll
            for (int d = 0; d < DIN; d++) {
                float xv = xs[r][d];
                a0 = fmaf(xv, ws[d * DEMB + j0    ], a0);
                a1 = fmaf(xv, ws[d * DEMB + j0 + 1], a1);
                a2 = fmaf(xv, ws[d * DEMB + j0 + 2], a2);
            }
            es[r][j0]     = fsigmoid(a0);
            es[r][j0 + 1] = fsigmoid(a1);
            es[r][j0 + 2] = fsigmoid(a2);
        }
        __syncthreads();

        // u[r][j*4+g] = e[r,:] @ Wg[0:24, j] + bg[j]  (fp16)
        {
            const int j = tid & 127;
            float wreg[4][DEMB];
#pragma unroll
            for (int d = 0; d < DEMB; d++) {
                wreg[0][d] = Wf[d * Hdim + j];
                wreg[1][d] = Wi[d * Hdim + j];
                wreg[2][d] = Wc[d * Hdim + j];
                wreg[3][d] = Wo[d * Hdim + j];
            }
            float bias[4] = { bf[j], bi[j], bc[j], bo[j] };

            const int rbase = (tid >> 7) * 16;
#pragma unroll 1
            for (int rr = 0; rr < 16; rr++) {
                int row = rbase + rr;
                float a0 = bias[0], a1 = bias[1], a2 = bias[2], a3 = bias[3];
#pragma unroll
                for (int d = 0; d < DEMB; d++) {
                    float ev = es[row][d];
                    a0 = fmaf(ev, wreg[0][d], a0);
                    a1 = fmaf(ev, wreg[1][d], a1);
                    a2 = fmaf(ev, wreg[2][d], a2);
                    a3 = fmaf(ev, wreg[3][d], a3);
                }
                __half2 lo = __floats2half2_rn(a0, a1);
                __half2 hi = __floats2half2_rn(a2, a3);
                uint2 v;
                v.x = *reinterpret_cast<uint32_t*>(&lo);
                v.y = *reinterpret_cast<uint32_t*>(&hi);
                *reinterpret_cast<uint2*>(g_u16 + ((r0 + row) * 512 + j * 4)) = v;
            }
        }

        __syncthreads();
        __threadfence();
        if (tid == 0) {
            volatile int* dn = g_done + b;
            while (*dn != k) { }            // predecessors have lower blockIdx
            *dn = k + 1;                    // publish prefix
        }
        return;
    }

    // ===================== SCAN =====================
    const int b  = blockIdx.x;
    const int t  = tid;                  // 0..255
    const int j  = t >> 1;               // hidden unit 0..127
    const int gp = t & 1;                // 0:{f,i}  1:{c,o}
    const unsigned FULL = 0xFFFFFFFFu;

    const float* WgA = gp ? Wc : Wf;     // slot 0: f or c
    const float* WgB = gp ? Wo : Wi;     // slot 1: i or o

    // Recurrent weights (rows 24..151, column j) for both gates, half2-packed
    __half2 wA[64], wB[64];
#pragma unroll
    for (int k = 0; k < 64; k++) {
        int row = DEMB + 2 * k;
        wA[k] = __floats2half2_rn(WgA[row * Hdim + j], WgA[(row + 1) * Hdim + j]);
        wB[k] = __floats2half2_rn(WgB[row * Hdim + j], WgB[(row + 1) * Hdim + j]);
    }

    // vector activation constants for this lane's two gates:
    //   gp0 = {f:sigmoid, i:sigmoid}  -> 0.5*tanh(0.5z)+0.5 in both halves
    //   gp1 = {g:tanh,    o:sigmoid}  -> (1*tanh(1z)+0, 0.5*tanh(0.5z)+0.5)
    const __half2 sc2 = gp ? __floats2half2_rn(1.f, 0.5f)
                           : __floats2half2_rn(0.5f, 0.5f);
    const __half2 aa2 = gp ? __floats2half2_rn(0.f, 0.5f)
                           : __floats2half2_rn(0.5f, 0.5f);

    __shared__ __align__(16) __half hbuf[2][Hdim];
    __shared__ float hfin[Hdim];

    if (t < Hdim) hbuf[0][t] = __float2half_rn(0.f);
    float c = 0.f, hkeep = 0.f;

    volatile int* dn = g_done + b;
    int ready = 0;                        // rows known complete = done[b]*32
    while (ready < 3) ready = (*dn) << 5; // rows 0..2 for the initial loads
    __threadfence();

    // u: this lane's two gate halves are half2 index t within the row;
    // row stride = 256 half2. Keep the pipeline as raw half2.
    const uint32_t* upw = reinterpret_cast<const uint32_t*>(
        g_u16 + ((size_t)b * Tlen) * 512) + t;
    uint32_t u_cur = upw[0];
    uint32_t u_n1  = upw[256];
    uint32_t u_n2  = upw[512];
    __syncthreads();

    const __half2 z2 = __floats2half2_rn(0.f, 0.f);

    auto step = [&](int s, int rd) {
        const int wrs = 1 - rd;
        // prefetch u for step s+3 (consumed ~2.5 steps later)
        uint32_t u_n3 = 0u;
        if (s + 3 < Tlen) u_n3 = upw[(size_t)(s + 3) * 256];

        // dual GEMV over h (16 broadcast LDS.128, 128 HFMA2)
        const uint4* hp = reinterpret_cast<const uint4*>(hbuf[rd]);
        __half2 aA0 = z2, aA1 = z2, aA2 = z2, aA3 = z2;
        __half2 aB0 = z2, aB1 = z2, aB2 = z2, aB3 = z2;
#pragma unroll
        for (int kk = 0; kk < 16; kk++) {
            union { uint4 v; __half2 h2[4]; } hv;
            hv.v = hp[kk];
            aA0 = __hfma2(wA[kk * 4 + 0], hv.h2[0], aA0);
            aA1 = __hfma2(wA[kk * 4 + 1], hv.h2[1], aA1);
            aA2 = __hfma2(wA[kk * 4 + 2], hv.h2[2], aA2);
            aA3 = __hfma2(wA[kk * 4 + 3], hv.h2[3], aA3);
            aB0 = __hfma2(wB[kk * 4 + 0], hv.h2[0], aB0);
            aB1 = __hfma2(wB[kk * 4 + 1], hv.h2[1], aB1);
            aB2 = __hfma2(wB[kk * 4 + 2], hv.h2[2], aB2);
            aB3 = __hfma2(wB[kk * 4 + 3], hv.h2[3], aB3);
        }
        __half2 rA = __hadd2(__hadd2(aA0, aA1), __hadd2(aA2, aA3));
        __half2 rB = __hadd2(__hadd2(aB0, aB1), __hadd2(aB2, aB3));

        // z for both gates as one half2: (sumA, sumB) + (uA, uB)
        __half2 lows  = __lows2half2(rA, rB);
        __half2 highs = __highs2half2(rA, rB);
        __half2 zh2   = __hadd2(__hadd2(lows, highs),
                                *reinterpret_cast<__half2*>(&u_cur));

        // shift u pipeline
        u_cur = u_n1; u_n1 = u_n2; u_n2 = u_n3;

        // vector activation: one tanh.approx.f16x2 covers both gates
        __half2 gv2 = __hfma2(sc2, tanh2fast(__hmul2(sc2, zh2)), aa2);

        // single packed exchange with partner lane
        uint32_t gvbits = *reinterpret_cast<uint32_t*>(&gv2);
        uint32_t ogbits = __shfl_xor_sync(FULL, gvbits, 1);
        __half2 og2 = *reinterpret_cast<__half2*>(&ogbits);

        __half2 fi2 = gp ? og2 : gv2;     // (f, i)
        __half2 go2 = gp ? gv2 : og2;     // (g, o)
        float2 fi = __half22float2(fi2);
        float2 go = __half22float2(go2);

        // redundant cell update (identical in both lanes of the pair)
        c = fmaf(c, fi.x, fi.y * go.x);
        float hn = tanhfast(c) * go.y;
        if (gp == 0) hbuf[wrs][j] = __float2half_rn(hn);
        hkeep = hn;
        __syncthreads();   // single barrier per step
    };

#pragma unroll 1
    for (int s = 0; s < Tlen; s += 2) {
        // guard prefetches for this pair: rows s+3 and s+4 (clamped at the end)
        int need = s + 4;
        if (need > Tlen - 1) need = Tlen - 1;
        if (ready <= need) {
            do { ready = (*dn) << 5; } while (ready <= need);
            __threadfence();
        }
        step(s, 0);
        step(s + 1, 1);
    }

    // final head: out[b] = sigmoid(h_T @ W_out + b_out)
    if (gp == 0) hfin[j] = hkeep * W_out[j];
    __syncthreads();
    if (t == 0) {
        float sacc = b_out[0];
#pragma unroll 1
        for (int k = 0; k < Hdim; k++) sacc += hfin[k];
        out[b] = fsigmoid(sacc);
        *dn = 0;                          // reset ticket for next graph replay
    }
}

// ---------------------------------------------------------------------------
// Launch
// inputs: 0:x 1:W_emb 2:b_emb 3:W_f 4:b_f 5:W_i 6:b_i 7:W_c 8:b_c
//         9:W_o 10:b_o 11:W_out 12:b_out
// ---------------------------------------------------------------------------
extern "C" void kernel_launch(void* const* d_in, const int* in_sizes, int n_in,
                              void* d_out, int out_size)
{
    const float* x     = (const float*)d_in[0];
    const float* W_emb = (const float*)d_in[1];
    const float* b_emb = (const float*)d_in[2];
    const float* W_f   = (const float*)d_in[3];
    const float* b_f   = (const float*)d_in[4];
    const float* W_i   = (const float*)d_in[5];
    const float* b_i   = (const float*)d_in[6];
    const float* W_c   = (const float*)d_in[7];
    const float* b_c   = (const float*)d_in[8];
    const float* W_o   = (const float*)d_in[9];
    const float* b_o   = (const float*)d_in[10];
    const float* W_out = (const float*)d_in[11];
    const float* b_out = (const float*)d_in[12];
    float* out = (float*)d_out;

    // 64 scan blocks + 64*128 producer blocks
    fused_kernel<<<64 + Bsz * (Tlen / 32), 256>>>(
        x, W_emb, b_emb, W_f, b_f, W_i, b_i, W_c, b_c, W_o, b_o,
        W_out, b_out, out);
}